// round 16
// baseline (speedup 1.0000x reference)
#include <cuda_runtime.h>
#include <math.h>

#define BB 64
#define NN 128
#define DD 512
#define D3 1536
#define NBLK 128

// ---------------- scratch (device globals; no allocation) ----------------
__device__ float g_gi[BB * NN * D3];      // x @ Wi_c^T + bi_c
__device__ float g_gh[BB * NN * D3];      // x @ Wh_p^T + bh_p
__device__ float g_qb[BB * NN];           // x . wq + lin_b
__device__ float g_hk2[2][BB * NN];       // H[b,n] . wk, split in two d-halves
__device__ float g_u[BB * 2 * DD];        // [u0 | u1] weighted sums (64 x 1024)
__device__ float g_M[BB * DD];            // M accumulated via RED (64 x 512)
__device__ float g_G[BB * 3072];          // gates = M @ [Wh_c;Wi_p]^T

// ---------------- hierarchical monotonic grid barrier ----------------
__device__ unsigned g_c1[8];              // group counters (16 blocks each)
__device__ unsigned g_c0;                 // root counter (8 groups)
__device__ volatile unsigned g_gen;       // release generation
__device__ volatile int g_ps[2][BB];      // sibling pair flags (value = phase)

__device__ __forceinline__ void grid_sync() {
    __syncthreads();
    if (threadIdx.x == 0) {
        __threadfence();
        unsigned gen = g_gen;
        unsigned grp = blockIdx.x >> 4;
        if (atomicAdd(&g_c1[grp], 1u) == gen * 16u + 15u) {
            if (atomicAdd(&g_c0, 1u) == gen * 8u + 7u) {
                __threadfence();
                g_gen = gen + 1u;
            }
        }
        while (g_gen == gen) { __nanosleep(32); }
    }
    __syncthreads();
}

__device__ __forceinline__ float gru_out(float ir, float iz, float inn,
                                         float hr, float hz, float hn, float h) {
    float r = 1.f / (1.f + expf(-(ir + hr)));
    float z = 1.f / (1.f + expf(-(iz + hz)));
    float n = tanhf(inn + r * hn);
    return (1.f - z) * n + z * h;
}

// ---------------- precompute GEMM: C[m,n] = sum_k A[m,k]*W[n,k] + bias[n] ----
__global__ __launch_bounds__(256) void gemm_nt_bias(
    const float* __restrict__ A, const float* __restrict__ W,
    const float* __restrict__ bias, int dst,
    int lda, int ldw, int ldc, int K)
{
    __shared__ __align__(16) float As[8][128];
    __shared__ __align__(16) float Ws[8][128];
    float* C = dst ? g_gh : g_gi;
    int t = threadIdx.x;
    int m0 = blockIdx.y * 128;
    int n0 = blockIdx.x * 128;
    int ar = t >> 1, ak = (t & 1) * 4;
    int ty = t >> 4, tx = t & 15;
    float acc[8][8];
#pragma unroll
    for (int i = 0; i < 8; i++)
#pragma unroll
        for (int j = 0; j < 8; j++) acc[i][j] = 0.f;

    for (int k0 = 0; k0 < K; k0 += 8) {
        float4 av = *(const float4*)(A + (size_t)(m0 + ar) * lda + k0 + ak);
        float4 wv = *(const float4*)(W + (size_t)(n0 + ar) * ldw + k0 + ak);
        As[ak + 0][ar] = av.x; As[ak + 1][ar] = av.y;
        As[ak + 2][ar] = av.z; As[ak + 3][ar] = av.w;
        Ws[ak + 0][ar] = wv.x; Ws[ak + 1][ar] = wv.y;
        Ws[ak + 2][ar] = wv.z; Ws[ak + 3][ar] = wv.w;
        __syncthreads();
#pragma unroll
        for (int k = 0; k < 8; k++) {
            float a[8], w[8];
            *(float4*)&a[0] = *(const float4*)&As[k][ty * 8];
            *(float4*)&a[4] = *(const float4*)&As[k][ty * 8 + 4];
            *(float4*)&w[0] = *(const float4*)&Ws[k][tx * 8];
            *(float4*)&w[4] = *(const float4*)&Ws[k][tx * 8 + 4];
#pragma unroll
            for (int i = 0; i < 8; i++)
#pragma unroll
                for (int j = 0; j < 8; j++) acc[i][j] += a[i] * w[j];
        }
        __syncthreads();
    }
#pragma unroll
    for (int i = 0; i < 8; i++) {
        int m = m0 + ty * 8 + i;
#pragma unroll
        for (int j = 0; j < 8; j++) {
            int n = n0 + tx * 8 + j;
            C[(size_t)m * ldc + n] = acc[i][j] + bias[n];
        }
    }
}

// ---------------- qb: g_qb[row] = features[row,:] . wq + lin_b -------------
__global__ __launch_bounds__(128) void qb_kernel(
    const float* __restrict__ feat, const float* __restrict__ lin_w,
    const float* __restrict__ lin_b)
{
    __shared__ float sred[128];
    int row = blockIdx.x;
    int t = threadIdx.x;
    const float* x = feat + (size_t)row * DD;
    float s = x[t] * lin_w[t] + x[t + 128] * lin_w[t + 128]
            + x[t + 256] * lin_w[t + 256] + x[t + 384] * lin_w[t + 384];
    sred[t] = s;
    __syncthreads();
    for (int st = 64; st > 0; st >>= 1) {
        if (t < st) sred[t] += sred[t + st];
        __syncthreads();
    }
    if (t == 0) g_qb[row] = sred[0] + lin_b[0];
}

// ---------------- fused attention for step j, sibling pair (b, half) --------
// Both siblings compute the same softmax; each accumulates u over its 256-d
// half, with the n-loop additionally split across thread halves.
__device__ __forceinline__ void attn_pair(
    int b, int half, int j, int t,
    const int* __restrict__ adj, const int* __restrict__ smask,
    const int* __restrict__ omask, const float* __restrict__ H,
    float* sa, float* sr, float* sws, float* swo, float* sU0, float* sU1)
{
    float a = -1e30f;
    int valid = 0;
    if (t < NN) {
        valid = (t < j) && adj[(size_t)(b * NN + j) * NN + t];
        if (valid)
            a = g_qb[b * NN + j] + __ldcg(&g_hk2[0][b * NN + t])
                                 + __ldcg(&g_hk2[1][b * NN + t]);
        sa[t] = a;
        sr[t] = a;
    }
    __syncthreads();
    for (int st = 64; st > 0; st >>= 1) {
        if (t < st) sr[t] = fmaxf(sr[t], sr[t + st]);
        __syncthreads();
    }
    float mx = sr[0];
    __syncthreads();
    float e = 0.f;
    if (t < NN) {
        e = valid ? expf(sa[t] - mx) : 0.f;
        sr[t] = e;
    }
    __syncthreads();
    for (int st = 64; st > 0; st >>= 1) {
        if (t < st) sr[t] += sr[t + st];
        __syncthreads();
    }
    float inv = 1.f / sr[0];
    if (t < NN) {
        float w = e * inv;
        int sm = 0, om = 0;
        if (valid) {
            sm = smask[(size_t)(b * NN + j) * NN + t];
            om = omask[(size_t)(b * NN + j) * NN + t];
        }
        sws[t] = w * (float)sm;
        swo[t] = w * (float)om;
    }
    __syncthreads();

    // u over this block's d-half; n split across thread halves
    int dd = t & 255, nh = t >> 8;
    int n0 = nh * 64, n1 = min(j, n0 + 64);
    float u0 = 0.f, u1 = 0.f;
    const float* Hb = H + (size_t)b * NN * DD + half * 256 + dd;
    for (int n = n0; n < n1; n++) {
        float ws = sws[n], wo = swo[n];
        if (ws == 0.f && wo == 0.f) continue;   // uniform branch (smem)
        float h = __ldcg(Hb + (size_t)n * DD);
        u0 += ws * h;
        u1 += wo * h;
    }
    sU0[t] = u0;
    sU1[t] = u1;
    __syncthreads();
    if (t < 256) {
        __stcg(&g_u[b * 1024 + half * 256 + t], sU0[t] + sU0[t + 256]);
        __stcg(&g_u[b * 1024 + 512 + half * 256 + t], sU1[t] + sU1[t + 256]);
    }
}

// ---------------- persistent recurrence kernel ------------------------------
__global__ __launch_bounds__(512, 1) void grn_loop(
    const float* __restrict__ feat,
    const float* __restrict__ bh_c, const float* __restrict__ bi_p,
    const float* __restrict__ lin_w,
    const int* __restrict__ adj, const int* __restrict__ smask,
    const int* __restrict__ omask,
    const float* __restrict__ Wr0, const float* __restrict__ Wr1,
    const float* __restrict__ Whc, const float* __restrict__ Wip,
    float* __restrict__ H)
{
    __shared__ float sA[32 * 65];
    __shared__ float sW[32 * 33];
    __shared__ float sa[128], sr[128], sws[128], swo[128];
    __shared__ float sred[256];
    __shared__ float sU0[512], sU1[512];

    int blk = blockIdx.x;
    int t = threadIdx.x;
    int b = blk >> 1, half = blk & 1;

    // ======== init: H[:,0], hk2[:,0], fused attn for step 1 (all blocks) ====
    {
        if (t < 256) {
            int d = half * 256 + t;
            const float* gi = g_gi + (size_t)(b * NN) * D3;
            const float* gh = g_gh + (size_t)(b * NN) * D3;
            float Cv = gru_out(gi[d], gi[512 + d], gi[1024 + d],
                               bh_c[d], bh_c[512 + d], bh_c[1024 + d], 0.f);
            float x0 = feat[(size_t)(b * NN) * DD + d];
            float Pv = gru_out(bi_p[d], bi_p[512 + d], bi_p[1024 + d],
                               gh[d], gh[512 + d], gh[1024 + d], x0);
            float Hv = Cv + Pv;
            __stcg(&H[(size_t)(b * NN) * DD + d], Hv);
            sred[t] = Hv * lin_w[512 + d];
        }
        __syncthreads();
        for (int st = 128; st > 0; st >>= 1) {
            if (t < st) sred[t] += sred[t + st];
            __syncthreads();
        }
        if (t == 0) {
            __stcg(&g_hk2[half][b * NN], sred[0]);
            __threadfence();
            g_ps[half][b] = 1;
            while (g_ps[half ^ 1][b] != 1) { __nanosleep(32); }
        }
        __syncthreads();
        attn_pair(b, half, 1, t, adj, smask, omask, H, sa, sr, sws, swo, sU0, sU1);
    }
    grid_sync();

    for (int i = 1; i < NN; i++) {
        // ======== B1: g_M += u @ [Wr0|Wr1]^T (split-K x8 via RED) ===========
        {
            int kseg = blk >> 4, cs = blk & 15;
            int c0 = cs * 32;
            const float* Wm = (kseg < 4) ? Wr0 : Wr1;
            int kw0 = kseg * 128 - (kseg < 4 ? 0 : 512);
            int lr = t >> 3, kq = (t & 7) * 4;
            int rg = t >> 3, cg = t & 7;
            float acc[4][4];
#pragma unroll
            for (int ii = 0; ii < 4; ii++)
#pragma unroll
                for (int jj = 0; jj < 4; jj++) acc[ii][jj] = 0.f;

            float4 va = __ldcg((const float4*)(g_u + lr * 1024 + kseg * 128 + kq));
            float4 vw;
            if (t < 256)
                vw = *(const float4*)(Wm + (size_t)(c0 + lr) * 512 + kw0 + kq);
            sA[(kq + 0) * 65 + lr] = va.x; sA[(kq + 1) * 65 + lr] = va.y;
            sA[(kq + 2) * 65 + lr] = va.z; sA[(kq + 3) * 65 + lr] = va.w;
            if (t < 256) {
                sW[(kq + 0) * 33 + lr] = vw.x; sW[(kq + 1) * 33 + lr] = vw.y;
                sW[(kq + 2) * 33 + lr] = vw.z; sW[(kq + 3) * 33 + lr] = vw.w;
            }
            __syncthreads();

            for (int kk = 0; kk < 128; kk += 32) {
                int more = (kk + 32 < 128);
                if (more) {
                    va = __ldcg((const float4*)(g_u + lr * 1024 + kseg * 128 + kk + 32 + kq));
                    if (t < 256)
                        vw = *(const float4*)(Wm + (size_t)(c0 + lr) * 512 + kw0 + kk + 32 + kq);
                }
                if (t < 128) {
#pragma unroll
                    for (int k = 0; k < 32; k++) {
                        float a0 = sA[k * 65 + rg * 4 + 0];
                        float a1 = sA[k * 65 + rg * 4 + 1];
                        float a2 = sA[k * 65 + rg * 4 + 2];
                        float a3 = sA[k * 65 + rg * 4 + 3];
                        float w0 = sW[k * 33 + cg * 4 + 0];
                        float w1 = sW[k * 33 + cg * 4 + 1];
                        float w2 = sW[k * 33 + cg * 4 + 2];
                        float w3 = sW[k * 33 + cg * 4 + 3];
                        acc[0][0] += a0 * w0; acc[0][1] += a0 * w1;
                        acc[0][2] += a0 * w2; acc[0][3] += a0 * w3;
                        acc[1][0] += a1 * w0; acc[1][1] += a1 * w1;
                        acc[1][2] += a1 * w2; acc[1][3] += a1 * w3;
                        acc[2][0] += a2 * w0; acc[2][1] += a2 * w1;
                        acc[2][2] += a2 * w2; acc[2][3] += a2 * w3;
                        acc[3][0] += a3 * w0; acc[3][1] += a3 * w1;
                        acc[3][2] += a3 * w2; acc[3][3] += a3 * w3;
                    }
                }
                __syncthreads();
                if (more) {
                    sA[(kq + 0) * 65 + lr] = va.x; sA[(kq + 1) * 65 + lr] = va.y;
                    sA[(kq + 2) * 65 + lr] = va.z; sA[(kq + 3) * 65 + lr] = va.w;
                    if (t < 256) {
                        sW[(kq + 0) * 33 + lr] = vw.x; sW[(kq + 1) * 33 + lr] = vw.y;
                        sW[(kq + 2) * 33 + lr] = vw.z; sW[(kq + 3) * 33 + lr] = vw.w;
                    }
                    __syncthreads();
                }
            }
            if (t < 128) {
#pragma unroll
                for (int ii = 0; ii < 4; ii++)
#pragma unroll
                    for (int jj = 0; jj < 4; jj++)
                        atomicAdd(&g_M[(size_t)(rg * 4 + ii) * 512 + c0 + cg * 4 + jj],
                                  acc[ii][jj]);
                __threadfence();   // drain REDs before barrier arrival
            }
        }
        grid_sync();

        // ======== B2: G = M @ [Wh_c;Wi_p]^T (128 blocks, 64x24 tiles) =======
        {
            int c0 = blk * 24;
            const float* Wg = (c0 < 1536) ? (Whc + (size_t)c0 * 512)
                                          : (Wip + (size_t)(c0 - 1536) * 512);
            int lr = t >> 3, kq = (t & 7) * 4;
            int rg = t >> 3, cg = t & 7;
            float acc[4][3];
#pragma unroll
            for (int ii = 0; ii < 4; ii++)
#pragma unroll
                for (int jj = 0; jj < 3; jj++) acc[ii][jj] = 0.f;

            float4 va = __ldcg((const float4*)(g_M + lr * 512 + kq));
            float4 vw;
            if (t < 192)
                vw = *(const float4*)(Wg + (size_t)lr * 512 + kq);
            sA[(kq + 0) * 65 + lr] = va.x; sA[(kq + 1) * 65 + lr] = va.y;
            sA[(kq + 2) * 65 + lr] = va.z; sA[(kq + 3) * 65 + lr] = va.w;
            if (t < 192) {
                sW[(kq + 0) * 25 + lr] = vw.x; sW[(kq + 1) * 25 + lr] = vw.y;
                sW[(kq + 2) * 25 + lr] = vw.z; sW[(kq + 3) * 25 + lr] = vw.w;
            }
            __syncthreads();

            for (int kk = 0; kk < 512; kk += 32) {
                int more = (kk + 32 < 512);
                if (more) {
                    va = __ldcg((const float4*)(g_M + lr * 512 + kk + 32 + kq));
                    if (t < 192)
                        vw = *(const float4*)(Wg + (size_t)lr * 512 + kk + 32 + kq);
                }
                if (t < 128) {
#pragma unroll
                    for (int k = 0; k < 32; k++) {
                        float a0 = sA[k * 65 + rg * 4 + 0];
                        float a1 = sA[k * 65 + rg * 4 + 1];
                        float a2 = sA[k * 65 + rg * 4 + 2];
                        float a3 = sA[k * 65 + rg * 4 + 3];
                        float w0 = sW[k * 25 + cg * 3 + 0];
                        float w1 = sW[k * 25 + cg * 3 + 1];
                        float w2 = sW[k * 25 + cg * 3 + 2];
                        acc[0][0] += a0 * w0; acc[0][1] += a0 * w1; acc[0][2] += a0 * w2;
                        acc[1][0] += a1 * w0; acc[1][1] += a1 * w1; acc[1][2] += a1 * w2;
                        acc[2][0] += a2 * w0; acc[2][1] += a2 * w1; acc[2][2] += a2 * w2;
                        acc[3][0] += a3 * w0; acc[3][1] += a3 * w1; acc[3][2] += a3 * w2;
                    }
                }
                __syncthreads();
                if (more) {
                    sA[(kq + 0) * 65 + lr] = va.x; sA[(kq + 1) * 65 + lr] = va.y;
                    sA[(kq + 2) * 65 + lr] = va.z; sA[(kq + 3) * 65 + lr] = va.w;
                    if (t < 192) {
                        sW[(kq + 0) * 25 + lr] = vw.x; sW[(kq + 1) * 25 + lr] = vw.y;
                        sW[(kq + 2) * 25 + lr] = vw.z; sW[(kq + 3) * 25 + lr] = vw.w;
                    }
                    __syncthreads();
                }
            }
            if (t < 128) {
#pragma unroll
                for (int ii = 0; ii < 4; ii++)
#pragma unroll
                    for (int jj = 0; jj < 3; jj++)
                        __stcg(&g_G[(size_t)(rg * 4 + ii) * 3072 + c0 + cg * 3 + jj],
                               acc[ii][jj]);
            }
        }
        grid_sync();

        // ======== CA: GRU -> H[:,i], hk2[:,i] (all 128 blocks, d split); ====
        // ======== zero g_M for next step; pair-sync; fused attn (i+1) =======
        {
            if (t < 256) {
                int d = half * 256 + t;
                float Mv = __ldcg(&g_M[b * 512 + d]);
                const float* gi = g_gi + (size_t)(b * NN + i) * D3;
                const float* gh = g_gh + (size_t)(b * NN + i) * D3;
                const float* gb = g_G + (size_t)b * 3072;
                float hr = __ldcg(&gb[d])        + bh_c[d];
                float hz = __ldcg(&gb[512 + d])  + bh_c[512 + d];
                float hn = __ldcg(&gb[1024 + d]) + bh_c[1024 + d];
                float Cv = gru_out(gi[d], gi[512 + d], gi[1024 + d], hr, hz, hn, Mv);
                float pir = __ldcg(&gb[1536 + d]) + bi_p[d];
                float piz = __ldcg(&gb[2048 + d]) + bi_p[512 + d];
                float pin = __ldcg(&gb[2560 + d]) + bi_p[1024 + d];
                float x = feat[(size_t)(b * NN + i) * DD + d];
                float Pv = gru_out(pir, piz, pin, gh[d], gh[512 + d], gh[1024 + d], x);
                float Hv = Cv + Pv;
                __stcg(&H[(size_t)(b * NN + i) * DD + d], Hv);
                __stcg(&g_M[b * 512 + d], 0.f);   // reset accumulator (after read)
                sred[t] = Hv * lin_w[512 + d];
            }
            __syncthreads();
            for (int st = 128; st > 0; st >>= 1) {
                if (t < st) sred[t] += sred[t + st];
                __syncthreads();
            }
            if (t == 0) {
                __stcg(&g_hk2[half][b * NN + i], sred[0]);
                __threadfence();
                g_ps[half][b] = i + 1;
                while (g_ps[half ^ 1][b] != i + 1) { __nanosleep(32); }
            }
            __syncthreads();
            if (i + 1 < NN)
                attn_pair(b, half, i + 1, t, adj, smask, omask, H,
                          sa, sr, sws, swo, sU0, sU1);
        }
        if (i + 1 < NN) grid_sync();
    }
}

// ---------------- launch ----------------------------------------------------
extern "C" void kernel_launch(void* const* d_in, const int* in_sizes, int n_in,
                              void* d_out, int out_size)
{
    const float* feat  = (const float*)d_in[0];
    const float* Wi_c  = (const float*)d_in[1];
    const float* Wh_c  = (const float*)d_in[2];
    const float* bi_c  = (const float*)d_in[3];
    const float* bh_c  = (const float*)d_in[4];
    const float* Wi_p  = (const float*)d_in[5];
    const float* Wh_p  = (const float*)d_in[6];
    const float* bi_p  = (const float*)d_in[7];
    const float* bh_p  = (const float*)d_in[8];
    const float* lin_w = (const float*)d_in[9];
    const float* lin_b = (const float*)d_in[10];
    const float* Wr0   = (const float*)d_in[11];
    const float* Wr1   = (const float*)d_in[12];
    const int*   adj   = (const int*)d_in[13];
    const int*   smask = (const int*)d_in[14];
    const int*   omask = (const int*)d_in[15];
    float* H = (float*)d_out;

    // Precompute x-side GRU gates for all (b, n)
    dim3 gpre(D3 / 128, (BB * NN) / 128);
    gemm_nt_bias<<<gpre, 256>>>(feat, Wi_c, bi_c, 0, DD, DD, D3, DD);
    gemm_nt_bias<<<gpre, 256>>>(feat, Wh_p, bh_p, 1, DD, DD, D3, DD);
    qb_kernel<<<BB * NN, 128>>>(feat, lin_w, lin_b);

    // Entire recurrence in one persistent kernel with hierarchical grid sync
    grn_loop<<<NBLK, 512>>>(feat, bh_c, bi_p, lin_w, adj, smask, omask,
                            Wr0, Wr1, Wh_c, Wi_p, H);
}

// round 17
// speedup vs baseline: 1.2595x; 1.2595x over previous
#include <cuda_runtime.h>
#include <math.h>

#define BB 64
#define NN 128
#define DD 512
#define D3 1536
#define NBLK 128

// ---------------- scratch (device globals; no allocation) ----------------
__device__ float g_gi[BB * NN * D3];      // x @ Wi_c^T + bi_c
__device__ float g_gh[BB * NN * D3];      // x @ Wh_p^T + bh_p
__device__ float g_qb[BB * NN];           // x . wq + lin_b
__device__ float g_hk[BB * NN];           // H[b,n] . wk (incremental)
__device__ float g_u[BB * 2 * DD];        // [u0 | u1] weighted sums (64 x 1024)
__device__ float g_Mpart[8 * BB * DD];    // split-K partials of M
__device__ float g_M[BB * DD];            // reduced M (64 x 512)
__device__ float g_G[BB * 3072];          // gates = M @ [Wh_c;Wi_p]^T

// ---------------- software grid barrier (Round-10/15 proven) ----------------
__device__ unsigned g_cnt = 0;
__device__ volatile unsigned g_gen = 0;

__device__ __forceinline__ void grid_sync() {
    __syncthreads();
    if (threadIdx.x == 0) {
        __threadfence();
        unsigned gen = g_gen;
        if (atomicAdd(&g_cnt, 1u) == NBLK - 1) {
            g_cnt = 0;
            __threadfence();
            g_gen = gen + 1;
        } else {
            while (g_gen == gen) { __nanosleep(64); }
        }
    }
    __syncthreads();
}

// ---------------- packed f32x2 helpers (FFMA2) ----------------
__device__ __forceinline__ unsigned long long pk2(float lo, float hi) {
    unsigned long long r;
    asm("mov.b64 %0, {%1, %2};" : "=l"(r)
        : "r"(__float_as_uint(lo)), "r"(__float_as_uint(hi)));
    return r;
}
__device__ __forceinline__ void fma2(unsigned long long& d,
                                     unsigned long long a, unsigned long long b) {
    asm("fma.rn.f32x2 %0, %1, %2, %0;" : "+l"(d) : "l"(a), "l"(b));
}
__device__ __forceinline__ float2 up2(unsigned long long p) {
    unsigned lo, hi;
    asm("mov.b64 {%0, %1}, %2;" : "=r"(lo), "=r"(hi) : "l"(p));
    return make_float2(__uint_as_float(lo), __uint_as_float(hi));
}

__device__ __forceinline__ float gru_out(float ir, float iz, float inn,
                                         float hr, float hz, float hn, float h) {
    float r = 1.f / (1.f + expf(-(ir + hr)));
    float z = 1.f / (1.f + expf(-(iz + hz)));
    float n = tanhf(inn + r * hn);
    return (1.f - z) * n + z * h;
}

// ---------------- precompute GEMM: C[m,n] = sum_k A[m,k]*W[n,k] + bias[n] ----
__global__ __launch_bounds__(256) void gemm_nt_bias(
    const float* __restrict__ A, const float* __restrict__ W,
    const float* __restrict__ bias, int dst,
    int lda, int ldw, int ldc, int K)
{
    __shared__ __align__(16) float As[8][128];
    __shared__ __align__(16) float Ws[8][128];
    float* C = dst ? g_gh : g_gi;
    int t = threadIdx.x;
    int m0 = blockIdx.y * 128;
    int n0 = blockIdx.x * 128;
    int ar = t >> 1, ak = (t & 1) * 4;
    int ty = t >> 4, tx = t & 15;
    unsigned long long acc2[8][4];
#pragma unroll
    for (int i = 0; i < 8; i++)
#pragma unroll
        for (int j = 0; j < 4; j++) acc2[i][j] = 0ull;

    for (int k0 = 0; k0 < K; k0 += 8) {
        float4 av = *(const float4*)(A + (size_t)(m0 + ar) * lda + k0 + ak);
        float4 wv = *(const float4*)(W + (size_t)(n0 + ar) * ldw + k0 + ak);
        As[ak + 0][ar] = av.x; As[ak + 1][ar] = av.y;
        As[ak + 2][ar] = av.z; As[ak + 3][ar] = av.w;
        Ws[ak + 0][ar] = wv.x; Ws[ak + 1][ar] = wv.y;
        Ws[ak + 2][ar] = wv.z; Ws[ak + 3][ar] = wv.w;
        __syncthreads();
#pragma unroll
        for (int k = 0; k < 8; k++) {
            float a[8], w[8];
            *(float4*)&a[0] = *(const float4*)&As[k][ty * 8];
            *(float4*)&a[4] = *(const float4*)&As[k][ty * 8 + 4];
            *(float4*)&w[0] = *(const float4*)&Ws[k][tx * 8];
            *(float4*)&w[4] = *(const float4*)&Ws[k][tx * 8 + 4];
            unsigned long long w2[4];
#pragma unroll
            for (int j = 0; j < 4; j++) w2[j] = pk2(w[2 * j], w[2 * j + 1]);
#pragma unroll
            for (int i = 0; i < 8; i++) {
                unsigned long long ai = pk2(a[i], a[i]);
#pragma unroll
                for (int j = 0; j < 4; j++) fma2(acc2[i][j], ai, w2[j]);
            }
        }
        __syncthreads();
    }
#pragma unroll
    for (int i = 0; i < 8; i++) {
        int m = m0 + ty * 8 + i;
#pragma unroll
        for (int j = 0; j < 4; j++) {
            int n = n0 + tx * 8 + 2 * j;
            float2 v = up2(acc2[i][j]);
            C[(size_t)m * ldc + n]     = v.x + bias[n];
            C[(size_t)m * ldc + n + 1] = v.y + bias[n + 1];
        }
    }
}

// ---------------- qb: g_qb[row] = features[row,:] . wq + lin_b -------------
__global__ __launch_bounds__(128) void qb_kernel(
    const float* __restrict__ feat, const float* __restrict__ lin_w,
    const float* __restrict__ lin_b)
{
    __shared__ float sred[128];
    int row = blockIdx.x;
    int t = threadIdx.x;
    const float* x = feat + (size_t)row * DD;
    float s = x[t] * lin_w[t] + x[t + 128] * lin_w[t + 128]
            + x[t + 256] * lin_w[t + 256] + x[t + 384] * lin_w[t + 384];
    sred[t] = s;
    __syncthreads();
    for (int st = 64; st > 0; st >>= 1) {
        if (t < st) sred[t] += sred[t + st];
        __syncthreads();
    }
    if (t == 0) g_qb[row] = sred[0] + lin_b[0];
}

// ---------------- fused attention for step j (block-local to batch b) -------
__device__ __forceinline__ void attn_u(
    int b, int j, int t,
    const int* __restrict__ adj, const int* __restrict__ smask,
    const int* __restrict__ omask, const float* __restrict__ H,
    float* sa, float* sr, float* sws, float* swo)
{
    float a = -1e30f;
    int valid = 0;
    if (t < NN) {
        valid = (t < j) && adj[(size_t)(b * NN + j) * NN + t];
        if (valid) a = g_qb[b * NN + j] + __ldcg(&g_hk[b * NN + t]);
        sa[t] = a;
        sr[t] = a;
    }
    __syncthreads();
    for (int st = 64; st > 0; st >>= 1) {
        if (t < st) sr[t] = fmaxf(sr[t], sr[t + st]);
        __syncthreads();
    }
    float mx = sr[0];
    __syncthreads();
    float e = 0.f;
    if (t < NN) {
        e = valid ? expf(sa[t] - mx) : 0.f;
        sr[t] = e;
    }
    __syncthreads();
    for (int st = 64; st > 0; st >>= 1) {
        if (t < st) sr[t] += sr[t + st];
        __syncthreads();
    }
    float inv = 1.f / sr[0];
    if (t < NN) {
        float w = e * inv;
        int sm = 0, om = 0;
        if (valid) {
            sm = smask[(size_t)(b * NN + j) * NN + t];
            om = omask[(size_t)(b * NN + j) * NN + t];
        }
        sws[t] = w * (float)sm;
        swo[t] = w * (float)om;
    }
    __syncthreads();

    // one H load feeds BOTH weighted sums (d = t, 0..511)
    float u0 = 0.f, u1 = 0.f;
    const float* Hb = H + (size_t)b * NN * DD + t;
    for (int n = 0; n < j; n++) {
        float ws = sws[n], wo = swo[n];
        if (ws == 0.f && wo == 0.f) continue;   // uniform branch (smem)
        float h = __ldcg(Hb + (size_t)n * DD);
        u0 += ws * h;
        u1 += wo * h;
    }
    __stcg(&g_u[b * 1024 + t], u0);
    __stcg(&g_u[b * 1024 + 512 + t], u1);
}

// ---------------- persistent recurrence kernel ------------------------------
__global__ __launch_bounds__(512, 1) void grn_loop(
    const float* __restrict__ feat,
    const float* __restrict__ bh_c, const float* __restrict__ bi_p,
    const float* __restrict__ lin_w,
    const int* __restrict__ adj, const int* __restrict__ smask,
    const int* __restrict__ omask,
    const float* __restrict__ Wr0, const float* __restrict__ Wr1,
    const float* __restrict__ Whc, const float* __restrict__ Wip,
    float* __restrict__ H)
{
    __shared__ __align__(16) float sA[32 * 66];   // even stride: float2 reads
    __shared__ __align__(16) float sW[32 * 34];
    __shared__ float sa[128], sr[128], sws[128], swo[128];
    __shared__ float sred[512];

    int blk = blockIdx.x;
    int t = threadIdx.x;

    // ======== init: H[:,0], hk[:,0], then fused A for step 1 (blocks < 64) ==
    if (blk < BB) {
        int b = blk, d = t;
        const float* gi = g_gi + (size_t)(b * NN) * D3;
        const float* gh = g_gh + (size_t)(b * NN) * D3;
        float Cv = gru_out(gi[d], gi[512 + d], gi[1024 + d],
                           bh_c[d], bh_c[512 + d], bh_c[1024 + d], 0.f);
        float x0 = feat[(size_t)(b * NN) * DD + d];
        float Pv = gru_out(bi_p[d], bi_p[512 + d], bi_p[1024 + d],
                           gh[d], gh[512 + d], gh[1024 + d], x0);
        float Hv = Cv + Pv;
        __stcg(&H[(size_t)(b * NN) * DD + d], Hv);
        sred[d] = Hv * lin_w[512 + d];
        __syncthreads();
        for (int st = 256; st > 0; st >>= 1) {
            if (d < st) sred[d] += sred[d + st];
            __syncthreads();
        }
        if (d == 0) __stcg(&g_hk[b * NN], sred[0]);
        __syncthreads();
        attn_u(b, 1, t, adj, smask, omask, H, sa, sr, sws, swo);
    }
    grid_sync();

    for (int i = 1; i < NN; i++) {
        // ======== B1: Mpart = u @ [Wr0|Wr1]^T (split-K x8, 128 blocks) ======
        // tile 64x32, micro 4x4 as 4x2 f32x2 pairs; t<128 compute
        {
            int kseg = blk >> 4, cs = blk & 15;
            int c0 = cs * 32;
            const float* Wm = (kseg < 4) ? Wr0 : Wr1;
            int kw0 = kseg * 128 - (kseg < 4 ? 0 : 512);
            int lr = t >> 3, kq = (t & 7) * 4;
            int rg = t >> 3, cg = t & 7;
            unsigned long long acc2[4][2];
#pragma unroll
            for (int ii = 0; ii < 4; ii++) { acc2[ii][0] = 0ull; acc2[ii][1] = 0ull; }

            float4 va = __ldcg((const float4*)(g_u + lr * 1024 + kseg * 128 + kq));
            float4 vw;
            if (t < 256)
                vw = *(const float4*)(Wm + (size_t)(c0 + lr) * 512 + kw0 + kq);
            sA[(kq + 0) * 66 + lr] = va.x; sA[(kq + 1) * 66 + lr] = va.y;
            sA[(kq + 2) * 66 + lr] = va.z; sA[(kq + 3) * 66 + lr] = va.w;
            if (t < 256) {
                sW[(kq + 0) * 34 + lr] = vw.x; sW[(kq + 1) * 34 + lr] = vw.y;
                sW[(kq + 2) * 34 + lr] = vw.z; sW[(kq + 3) * 34 + lr] = vw.w;
            }
            __syncthreads();

            for (int kk = 0; kk < 128; kk += 32) {
                int more = (kk + 32 < 128);
                if (more) {
                    va = __ldcg((const float4*)(g_u + lr * 1024 + kseg * 128 + kk + 32 + kq));
                    if (t < 256)
                        vw = *(const float4*)(Wm + (size_t)(c0 + lr) * 512 + kw0 + kk + 32 + kq);
                }
                if (t < 128) {
#pragma unroll
                    for (int k = 0; k < 32; k++) {
                        float2 a01 = *(const float2*)&sA[k * 66 + rg * 4];
                        float2 a23 = *(const float2*)&sA[k * 66 + rg * 4 + 2];
                        float2 w01 = *(const float2*)&sW[k * 34 + cg * 4];
                        float2 w23 = *(const float2*)&sW[k * 34 + cg * 4 + 2];
                        unsigned long long wA = pk2(w01.x, w01.y);
                        unsigned long long wB = pk2(w23.x, w23.y);
                        unsigned long long a0 = pk2(a01.x, a01.x);
                        unsigned long long a1 = pk2(a01.y, a01.y);
                        unsigned long long a2 = pk2(a23.x, a23.x);
                        unsigned long long a3 = pk2(a23.y, a23.y);
                        fma2(acc2[0][0], a0, wA); fma2(acc2[0][1], a0, wB);
                        fma2(acc2[1][0], a1, wA); fma2(acc2[1][1], a1, wB);
                        fma2(acc2[2][0], a2, wA); fma2(acc2[2][1], a2, wB);
                        fma2(acc2[3][0], a3, wA); fma2(acc2[3][1], a3, wB);
                    }
                }
                __syncthreads();
                if (more) {
                    sA[(kq + 0) * 66 + lr] = va.x; sA[(kq + 1) * 66 + lr] = va.y;
                    sA[(kq + 2) * 66 + lr] = va.z; sA[(kq + 3) * 66 + lr] = va.w;
                    if (t < 256) {
                        sW[(kq + 0) * 34 + lr] = vw.x; sW[(kq + 1) * 34 + lr] = vw.y;
                        sW[(kq + 2) * 34 + lr] = vw.z; sW[(kq + 3) * 34 + lr] = vw.w;
                    }
                    __syncthreads();
                }
            }
            if (t < 128) {
#pragma unroll
                for (int ii = 0; ii < 4; ii++) {
                    float2 v0 = up2(acc2[ii][0]);
                    float2 v1 = up2(acc2[ii][1]);
                    size_t base = (size_t)(kseg * 64 + rg * 4 + ii) * 512 + c0 + cg * 4;
                    __stcg(&g_Mpart[base + 0], v0.x);
                    __stcg(&g_Mpart[base + 1], v0.y);
                    __stcg(&g_Mpart[base + 2], v1.x);
                    __stcg(&g_Mpart[base + 3], v1.y);
                }
            }
        }
        grid_sync();

        // ======== R: reduce Mpart -> M (all 128 blocks, 256 elems each) =====
        if (t < 256) {
            int idx = blk * 256 + t;
            float s = 0.f;
#pragma unroll
            for (int ks = 0; ks < 8; ks++)
                s += __ldcg(&g_Mpart[(size_t)ks * BB * DD + idx]);
            __stcg(&g_M[idx], s);
        }
        grid_sync();

        // ======== B2: G = M @ [Wh_c;Wi_p]^T (128 blocks, 64x24 tiles) =======
        // micro 2x6 as 2x3 f32x2 pairs; thread grid 32x4; t<128 compute
        {
            int c0 = blk * 24;
            const float* Wg = (c0 < 1536) ? (Whc + (size_t)c0 * 512)
                                          : (Wip + (size_t)(c0 - 1536) * 512);
            int lr = t >> 3, kq = (t & 7) * 4;
            int rg = t >> 2, cg = t & 3;   // rg 0..31 (x2 rows), cg 0..3 (x6 cols)
            unsigned long long acc2[2][3];
#pragma unroll
            for (int ii = 0; ii < 2; ii++)
#pragma unroll
                for (int jj = 0; jj < 3; jj++) acc2[ii][jj] = 0ull;

            float4 va = __ldcg((const float4*)(g_M + lr * 512 + kq));
            float4 vw;
            if (t < 192)
                vw = *(const float4*)(Wg + (size_t)lr * 512 + kq);
            sA[(kq + 0) * 66 + lr] = va.x; sA[(kq + 1) * 66 + lr] = va.y;
            sA[(kq + 2) * 66 + lr] = va.z; sA[(kq + 3) * 66 + lr] = va.w;
            if (t < 192) {
                sW[(kq + 0) * 26 + lr] = vw.x; sW[(kq + 1) * 26 + lr] = vw.y;
                sW[(kq + 2) * 26 + lr] = vw.z; sW[(kq + 3) * 26 + lr] = vw.w;
            }
            __syncthreads();

            for (int kk = 0; kk < 512; kk += 32) {
                int more = (kk + 32 < 512);
                if (more) {
                    va = __ldcg((const float4*)(g_M + lr * 512 + kk + 32 + kq));
                    if (t < 192)
                        vw = *(const float4*)(Wg + (size_t)lr * 512 + kk + 32 + kq);
                }
                if (t < 128) {
#pragma unroll
                    for (int k = 0; k < 32; k++) {
                        float2 a01 = *(const float2*)&sA[k * 66 + rg * 2];
                        float2 w01 = *(const float2*)&sW[k * 26 + cg * 6];
                        float2 w23 = *(const float2*)&sW[k * 26 + cg * 6 + 2];
                        float2 w45 = *(const float2*)&sW[k * 26 + cg * 6 + 4];
                        unsigned long long W0 = pk2(w01.x, w01.y);
                        unsigned long long W1 = pk2(w23.x, w23.y);
                        unsigned long long W2 = pk2(w45.x, w45.y);
                        unsigned long long A0 = pk2(a01.x, a01.x);
                        unsigned long long A1 = pk2(a01.y, a01.y);
                        fma2(acc2[0][0], A0, W0); fma2(acc2[0][1], A0, W1);
                        fma2(acc2[0][2], A0, W2);
                        fma2(acc2[1][0], A1, W0); fma2(acc2[1][1], A1, W1);
                        fma2(acc2[1][2], A1, W2);
                    }
                }
                __syncthreads();
                if (more) {
                    sA[(kq + 0) * 66 + lr] = va.x; sA[(kq + 1) * 66 + lr] = va.y;
                    sA[(kq + 2) * 66 + lr] = va.z; sA[(kq + 3) * 66 + lr] = va.w;
                    if (t < 192) {
                        sW[(kq + 0) * 26 + lr] = vw.x; sW[(kq + 1) * 26 + lr] = vw.y;
                        sW[(kq + 2) * 26 + lr] = vw.z; sW[(kq + 3) * 26 + lr] = vw.w;
                    }
                    __syncthreads();
                }
            }
            if (t < 128) {
#pragma unroll
                for (int ii = 0; ii < 2; ii++) {
                    size_t base = (size_t)(rg * 2 + ii) * 3072 + c0 + cg * 6;
#pragma unroll
                    for (int jh = 0; jh < 3; jh++) {
                        float2 v = up2(acc2[ii][jh]);
                        __stcg(&g_G[base + 2 * jh + 0], v.x);
                        __stcg(&g_G[base + 2 * jh + 1], v.y);
                    }
                }
            }
        }
        grid_sync();

        // ======== CA: GRU -> H[:,i], hk[:,i]; then fused A for step i+1 =====
        if (blk < BB) {
            int b = blk, d = t;
            float Mv = __ldcg(&g_M[b * 512 + d]);
            const float* gi = g_gi + (size_t)(b * NN + i) * D3;
            const float* gh = g_gh + (size_t)(b * NN + i) * D3;
            const float* gb = g_G + (size_t)b * 3072;
            float hr = __ldcg(&gb[d])        + bh_c[d];
            float hz = __ldcg(&gb[512 + d])  + bh_c[512 + d];
            float hn = __ldcg(&gb[1024 + d]) + bh_c[1024 + d];
            float Cv = gru_out(gi[d], gi[512 + d], gi[1024 + d], hr, hz, hn, Mv);
            float pir = __ldcg(&gb[1536 + d]) + bi_p[d];
            float piz = __ldcg(&gb[2048 + d]) + bi_p[512 + d];
            float pin = __ldcg(&gb[2560 + d]) + bi_p[1024 + d];
            float x = feat[(size_t)(b * NN + i) * DD + d];
            float Pv = gru_out(pir, piz, pin, gh[d], gh[512 + d], gh[1024 + d], x);
            float Hv = Cv + Pv;
            __stcg(&H[(size_t)(b * NN + i) * DD + d], Hv);
            sred[d] = Hv * lin_w[512 + d];
            __syncthreads();
            for (int st = 256; st > 0; st >>= 1) {
                if (d < st) sred[d] += sred[d + st];
                __syncthreads();
            }
            if (d == 0) __stcg(&g_hk[b * NN + i], sred[0]);
            __syncthreads();
            if (i + 1 < NN)
                attn_u(b, i + 1, t, adj, smask, omask, H, sa, sr, sws, swo);
        }
        if (i + 1 < NN) grid_sync();
    }
}

// ---------------- launch ----------------------------------------------------
extern "C" void kernel_launch(void* const* d_in, const int* in_sizes, int n_in,
                              void* d_out, int out_size)
{
    const float* feat  = (const float*)d_in[0];
    const float* Wi_c  = (const float*)d_in[1];
    const float* Wh_c  = (const float*)d_in[2];
    const float* bi_c  = (const float*)d_in[3];
    const float* bh_c  = (const float*)d_in[4];
    const float* Wi_p  = (const float*)d_in[5];
    const float* Wh_p  = (const float*)d_in[6];
    const float* bi_p  = (const float*)d_in[7];
    const float* bh_p  = (const float*)d_in[8];
    const float* lin_w = (const float*)d_in[9];
    const float* lin_b = (const float*)d_in[10];
    const float* Wr0   = (const float*)d_in[11];
    const float* Wr1   = (const float*)d_in[12];
    const int*   adj   = (const int*)d_in[13];
    const int*   smask = (const int*)d_in[14];
    const int*   omask = (const int*)d_in[15];
    float* H = (float*)d_out;

    // Precompute x-side GRU gates for all (b, n)
    dim3 gpre(D3 / 128, (BB * NN) / 128);
    gemm_nt_bias<<<gpre, 256>>>(feat, Wi_c, bi_c, 0, DD, DD, D3, DD);
    gemm_nt_bias<<<gpre, 256>>>(feat, Wh_p, bh_p, 1, DD, DD, D3, DD);
    qb_kernel<<<BB * NN, 128>>>(feat, lin_w, lin_b);

    // Entire recurrence in one persistent kernel with grid-wide sync
    grn_loop<<<NBLK, 512>>>(feat, bh_c, bi_p, lin_w, adj, smask, omask,
                            Wr0, Wr1, Wh_c, Wi_p, H);
}